// round 2
// baseline (speedup 1.0000x reference)
#include <cuda_runtime.h>
#include <cstdint>

// Problem constants
// x:     (128, 9, 84, 420) fp32
// shift: (128, 2) int32, values in [0, 8]
// out:   (128, 9, 84, 420) fp32
// out[n,c,i,j] = x[n,c, yy, xx]
//   yy = clamp(ky + i - 4, 0, 419) % 84   (range of ky+i-4 is [-4, 87])
//   xx = clamp(kx + j - 4, 0, 419)
// with kx = shift[n,0], ky = shift[n,1]

#define N_   128
#define C_   9
#define H_   84
#define W_   420
#define W4_  (W_ / 4)                 // 105 float4 per row
#define ROWS (N_ * C_ * H_)           // 96768
#define TOTAL4 (ROWS * W4_)           // 10,160,640 float4 outputs

__global__ void __launch_bounds__(256)
random_shifts_kernel(const float* __restrict__ x,
                     const int*   __restrict__ shift,
                     float*       __restrict__ out)
{
    int t = blockIdx.x * blockDim.x + threadIdx.x;
    if (t >= TOTAL4) return;

    int j4  = t % W4_;
    int row = t / W4_;          // row = (n*C + c)*H + i
    int i   = row % H_;
    int nc  = row / H_;         // n*C + c
    int n   = nc / C_;

    int kx = __ldg(&shift[2 * n + 0]);
    int ky = __ldg(&shift[2 * n + 1]);

    // vertical index: clamp at 0 (upper clamp at 419 never binds), then mod 84
    int yy = ky + i - 4;
    yy = max(yy, 0);
    if (yy >= H_) yy -= H_;

    const float* src = x + ((size_t)nc * H_ + yy) * W_;

    int j = j4 * 4;
    int b = kx + j - 4;         // unclamped source column of element 0

    float4 v;
    int x0 = min(max(b + 0, 0), W_ - 1);
    int x1 = min(max(b + 1, 0), W_ - 1);
    int x2 = min(max(b + 2, 0), W_ - 1);
    int x3 = min(max(b + 3, 0), W_ - 1);
    v.x = __ldg(src + x0);
    v.y = __ldg(src + x1);
    v.z = __ldg(src + x2);
    v.w = __ldg(src + x3);

    reinterpret_cast<float4*>(out)[t] = v;
}

extern "C" void kernel_launch(void* const* d_in, const int* in_sizes, int n_in,
                              void* d_out, int out_size)
{
    const float* x     = (const float*)d_in[0];
    const int*   shift = (const int*)d_in[1];
    float*       out   = (float*)d_out;

    const int threads = 256;
    const int blocks  = (TOTAL4 + threads - 1) / threads;
    random_shifts_kernel<<<blocks, threads>>>(x, shift, out);
}